// round 5
// baseline (speedup 1.0000x reference)
#include <cuda_runtime.h>
#include <cuda_bf16.h>
#include <math.h>
#include <stdint.h>

#define NB 2
#define SQ 2048
#define NTOK 4096
#define DM 512
#define NH 8
#define DK 64
#define NL 6
#define DFF 2048
#define NV 1024
#define QKVW 1536

// ---------------- scratch ----------------
__device__ float    g_x  [NTOK * DM];
__device__ float    g_qkv[NTOK * QKVW];
__device__ uint32_t g_hh[NTOK * DM / 2],  g_hl[NTOK * DM / 2];    // LN out (split)
__device__ uint32_t g_ah[NTOK * DM / 2],  g_al[NTOK * DM / 2];    // attn out (split)
__device__ uint32_t g_fh[NTOK * DFF / 2], g_fl[NTOK * DFF / 2];   // ff (split)
__device__ uint32_t g_xh[NTOK * DM / 2],  g_xl[NTOK * DM / 2];    // x (split, for logits)
__device__ uint32_t g_wqkvh[NL * QKVW * DM / 2], g_wqkvl[NL * QKVW * DM / 2];
__device__ uint32_t g_woh[NL * DM * DM / 2],     g_wol[NL * DM * DM / 2];
__device__ uint32_t g_w1h[NL * DM * DFF / 2],    g_w1l[NL * DM * DFF / 2];
__device__ uint32_t g_w2h[NL * DM * DFF / 2],    g_w2l[NL * DM * DFF / 2];
__device__ uint32_t g_owh[NV * DM / 2],          g_owl[NV * DM / 2];
__device__ float    g_bqkv[NL * QKVW];

// ---------------- helpers ----------------
__device__ __forceinline__ uint32_t f2tf(float f) {
    uint32_t r;
    asm("cvt.rna.tf32.f32 %0, %1;" : "=r"(r) : "f"(f));
    return r;
}
__device__ __forceinline__ void split2(float v0, float v1, uint32_t& hi, uint32_t& lo) {
    __nv_bfloat16 h0 = __float2bfloat16(v0), h1 = __float2bfloat16(v1);
    __nv_bfloat16 g0 = __float2bfloat16(v0 - __bfloat162float(h0));
    __nv_bfloat16 g1 = __float2bfloat16(v1 - __bfloat162float(h1));
    hi = (uint32_t)__bfloat16_as_ushort(h0) | ((uint32_t)__bfloat16_as_ushort(h1) << 16);
    lo = (uint32_t)__bfloat16_as_ushort(g0) | ((uint32_t)__bfloat16_as_ushort(g1) << 16);
}
__device__ __forceinline__ void mma8(float* c, const uint32_t* a, const uint32_t* b) {
    asm volatile(
        "mma.sync.aligned.m16n8k8.row.col.f32.tf32.tf32.f32 "
        "{%0,%1,%2,%3}, {%4,%5,%6,%7}, {%8,%9}, {%0,%1,%2,%3};\n"
        : "+f"(c[0]), "+f"(c[1]), "+f"(c[2]), "+f"(c[3])
        : "r"(a[0]), "r"(a[1]), "r"(a[2]), "r"(a[3]), "r"(b[0]), "r"(b[1]));
}
__device__ __forceinline__ void mma16(float* c, const uint32_t* a, const uint32_t* b) {
    asm volatile(
        "mma.sync.aligned.m16n8k16.row.col.f32.bf16.bf16.f32 "
        "{%0,%1,%2,%3}, {%4,%5,%6,%7}, {%8,%9}, {%0,%1,%2,%3};\n"
        : "+f"(c[0]), "+f"(c[1]), "+f"(c[2]), "+f"(c[3])
        : "r"(a[0]), "r"(a[1]), "r"(a[2]), "r"(a[3]), "r"(b[0]), "r"(b[1]));
}
__device__ __forceinline__ void cpa16(uint32_t dst, const void* src) {
    asm volatile("cp.async.cg.shared.global [%0], [%1], 16;" :: "r"(dst), "l"(src));
}
#define CP_COMMIT() asm volatile("cp.async.commit_group;" ::: "memory")
#define CP_WAIT(n)  asm volatile("cp.async.wait_group %0;" :: "n"(n) : "memory")
__device__ __forceinline__ uint32_t smem_u32(const void* p) {
    uint32_t a;
    asm("{ .reg .u64 t; cvta.to.shared.u64 t, %1; cvt.u32.u64 %0, t; }" : "=r"(a) : "l"(p));
    return a;
}

// ---------------- split-bf16 GEMM ----------------
// C[4096,M] = A[4096,K] @ B[M,K]^T + bias. A,B given as bf16 hi/lo u32 planes
// (u32 = k-even|k-odd). CTA 128x128, chunk 32 floats (16 u32), 3-stage cp.async.
#define GPITCH 20
#define GREG 2560
#define GST 10240
#define GEMM_SMEM (3 * GST * 4)

__global__ __launch_bounds__(256) void gemm_bs(
    const uint32_t* __restrict__ Ah, const uint32_t* __restrict__ Al,
    const uint32_t* __restrict__ Bh, const uint32_t* __restrict__ Bl,
    const float* __restrict__ bias, const float* __restrict__ R,
    float* __restrict__ C, uint32_t* __restrict__ Ch, uint32_t* __restrict__ Cl,
    int K2, int M, int relu)
{
    extern __shared__ uint32_t sm[];
    uint32_t sb = smem_u32(sm);
    int t = threadIdx.x, lane = t & 31, wid = t >> 5;
    int wm = wid & 1, wn = wid >> 1;
    int gr = lane >> 2, tg = lane & 3;
    int row0 = blockIdx.y * 128, col0 = blockIdx.x * 128;
    const int NC = K2 >> 4;

    int reg = t >> 6, li = t & 63;
    const uint32_t* gsrc = (reg == 0) ? Ah : (reg == 1) ? Al : (reg == 2) ? Bh : Bl;
    const uint32_t* gbase = gsrc + (size_t)((reg < 2) ? row0 : col0) * K2;

    float acc[4][4][4];
    #pragma unroll
    for (int i = 0; i < 4; i++)
        #pragma unroll
        for (int j = 0; j < 4; j++)
            #pragma unroll
            for (int k = 0; k < 4; k++) acc[i][j][k] = 0.f;

    auto issue = [&](int c, int st) {
        uint32_t dbase = sb + (st * GST + reg * GREG) * 4;
        const uint32_t* s0 = gbase + c * 16;
        #pragma unroll
        for (int j = 0; j < 8; j++) {
            int seg = j * 64 + li, r = seg >> 2, p = seg & 3;
            cpa16(dbase + (r * GPITCH + p * 4) * 4, s0 + (size_t)r * K2 + p * 4);
        }
    };

    issue(0, 0); CP_COMMIT();
    if (NC > 1) { issue(1, 1); CP_COMMIT(); }

    for (int c = 0; c < NC; c++) {
        if (c + 1 < NC) { CP_WAIT(1); } else { CP_WAIT(0); }
        __syncthreads();
        if (c + 2 < NC) { issue(c + 2, (c + 2) % 3); CP_COMMIT(); }

        const uint32_t* S = sm + (c % 3) * GST;
        const uint32_t* sAh = S, *sAl = S + GREG, *sBh = S + 2 * GREG, *sBl = S + 3 * GREG;
        #pragma unroll
        for (int ks = 0; ks < 2; ks++) {
            int cb = ks * 8;
            uint32_t ah[4][4], al[4][4], bh[4][2], bl[4][2];
            #pragma unroll
            for (int mt = 0; mt < 4; mt++) {
                int r = wm * 64 + mt * 16 + gr;
                const uint32_t* p = sAh + r * GPITCH + cb + tg;
                ah[mt][0] = p[0]; ah[mt][2] = p[4];
                ah[mt][1] = p[8 * GPITCH]; ah[mt][3] = p[8 * GPITCH + 4];
                const uint32_t* q = sAl + r * GPITCH + cb + tg;
                al[mt][0] = q[0]; al[mt][2] = q[4];
                al[mt][1] = q[8 * GPITCH]; al[mt][3] = q[8 * GPITCH + 4];
            }
            #pragma unroll
            for (int nt = 0; nt < 4; nt++) {
                int r = wn * 32 + nt * 8 + gr;
                const uint32_t* p = sBh + r * GPITCH + cb + tg;
                bh[nt][0] = p[0]; bh[nt][1] = p[4];
                const uint32_t* q = sBl + r * GPITCH + cb + tg;
                bl[nt][0] = q[0]; bl[nt][1] = q[4];
            }
            #pragma unroll
            for (int mt = 0; mt < 4; mt++)
                #pragma unroll
                for (int nt = 0; nt < 4; nt++) {
                    mma16(acc[mt][nt], ah[mt], bh[nt]);
                    mma16(acc[mt][nt], ah[mt], bl[nt]);
                    mma16(acc[mt][nt], al[mt], bh[nt]);
                }
        }
    }

    int cpitch = M >> 1;
    #pragma unroll
    for (int mt = 0; mt < 4; mt++) {
        int r0 = row0 + wm * 64 + mt * 16 + gr;
        #pragma unroll
        for (int nt = 0; nt < 4; nt++) {
            int cc = col0 + wn * 32 + nt * 8 + tg * 2;
            float b0 = bias[cc], b1 = bias[cc + 1];
            #pragma unroll
            for (int h2 = 0; h2 < 2; h2++) {
                int rr = r0 + h2 * 8;
                size_t off = (size_t)rr * M + cc;
                float v0 = acc[mt][nt][h2 * 2 + 0] + b0;
                float v1 = acc[mt][nt][h2 * 2 + 1] + b1;
                if (R) { float2 rv = *(const float2*)(R + off); v0 += rv.x; v1 += rv.y; }
                if (relu) { v0 = fmaxf(v0, 0.f); v1 = fmaxf(v1, 0.f); }
                if (C) *(float2*)(C + off) = make_float2(v0, v1);
                if (Ch) {
                    uint32_t hi, lo;
                    split2(v0, v1, hi, lo);
                    size_t po = (size_t)rr * cpitch + (cc >> 1);
                    Ch[po] = hi; Cl[po] = lo;
                }
            }
        }
    }
}

// ---------------- flash attention (tf32 mma, round-3 proven) ----------------
// epilogue now writes split-bf16 planes (pitch 256 u32).
#define AP 68
#define ATTN_SMEM ((3 * 64 * AP + 192) * 4)

__global__ __launch_bounds__(128) void attn_mma(const float* __restrict__ qkv,
                                                uint32_t* __restrict__ oh,
                                                uint32_t* __restrict__ ol) {
    extern __shared__ uint32_t smu[];
    uint32_t* Qs = smu;
    uint32_t* Ks = smu + 64 * AP;
    float*    Ps = (float*)(smu + 2 * 64 * AP);
    float*  sm_m = (float*)(smu + 3 * 64 * AP);
    float*  sm_l = sm_m + 64;
    float* sm_rs = sm_m + 128;

    int qt = blockIdx.x, bh = blockIdx.y, bb = bh >> 3, hh = bh & 7;
    int t = threadIdx.x, lane = t & 31, wid = t >> 5;
    int gr = lane >> 2, lc = lane & 3;
    int mrow = wid * 16 + gr;
    const size_t base = (size_t)bb * SQ * QKVW + hh * DK;

    const float* qb = qkv + base + (size_t)qt * 64 * QKVW;
    #pragma unroll
    for (int i = 0; i < 8; i++) {
        int f = i * 128 + t, r = f >> 4, d4 = (f & 15) << 2;
        float4 v = *(const float4*)(qb + (size_t)r * QKVW + d4);
        *(uint4*)(Qs + r * AP + d4) = make_uint4(f2tf(v.x), f2tf(v.y), f2tf(v.z), f2tf(v.w));
    }
    if (t < 64) { sm_m[t] = -1e30f; sm_l[t] = 0.f; }

    float co[8][4];
    #pragma unroll
    for (int i = 0; i < 8; i++)
        #pragma unroll
        for (int j = 0; j < 4; j++) co[i][j] = 0.f;

    for (int kt = 0; kt <= qt; kt++) {
        __syncthreads();
        const float* kb = qkv + base + 512 + (size_t)kt * 64 * QKVW;
        #pragma unroll
        for (int i = 0; i < 8; i++) {
            int f = i * 128 + t, r = f >> 4, d4 = (f & 15) << 2;
            float4 v = *(const float4*)(kb + (size_t)r * QKVW + d4);
            *(uint4*)(Ks + r * AP + d4) = make_uint4(f2tf(v.x), f2tf(v.y), f2tf(v.z), f2tf(v.w));
        }
        __syncthreads();

        float cs[8][4];
        #pragma unroll
        for (int i = 0; i < 8; i++)
            #pragma unroll
            for (int j = 0; j < 4; j++) cs[i][j] = 0.f;
        {
            const uint32_t* Abase = Qs + mrow * AP + lc;
            const uint32_t* Bbase = Ks + gr * AP + lc;
            #pragma unroll
            for (int ks = 0; ks < 8; ks++) {
                uint32_t a[4];
                const uint32_t* p = Abase + ks * 8;
                a[0] = p[0]; a[1] = p[8 * AP]; a[2] = p[4]; a[3] = p[8 * AP + 4];
                #pragma unroll
                for (int nt = 0; nt < 8; nt++) {
                    const uint32_t* q2 = Bbase + nt * 8 * AP + ks * 8;
                    uint32_t b[2] = {q2[0], q2[4]};
                    mma8(cs[nt], a, b);
                }
            }
        }
        #pragma unroll
        for (int nt = 0; nt < 8; nt++) {
            int c = nt * 8 + lc * 2;
            *(float2*)(Ps + mrow * AP + c)       = make_float2(cs[nt][0], cs[nt][1]);
            *(float2*)(Ps + (mrow + 8) * AP + c) = make_float2(cs[nt][2], cs[nt][3]);
        }
        __syncthreads();

        {
            int r = t >> 1, half = t & 1;
            int qrow = qt * 64 + r;
            int kbase0 = kt * 64 + half * 32;
            float* rowp = Ps + r * AP + half * 32;
            float vals[32];
            float mx = -1e30f;
            bool edge = (kt == qt);
            #pragma unroll
            for (int j = 0; j < 32; j += 4) {
                float4 v4 = *(const float4*)(rowp + j);
                float w0 = v4.x * 0.125f, w1 = v4.y * 0.125f;
                float w2 = v4.z * 0.125f, w3 = v4.w * 0.125f;
                if (edge) {
                    if (kbase0 + j + 0 > qrow) w0 = -1e30f;
                    if (kbase0 + j + 1 > qrow) w1 = -1e30f;
                    if (kbase0 + j + 2 > qrow) w2 = -1e30f;
                    if (kbase0 + j + 3 > qrow) w3 = -1e30f;
                }
                vals[j] = w0; vals[j+1] = w1; vals[j+2] = w2; vals[j+3] = w3;
                mx = fmaxf(mx, fmaxf(fmaxf(w0, w1), fmaxf(w2, w3)));
            }
            mx = fmaxf(mx, __shfl_xor_sync(0xffffffffu, mx, 1));
            float mo = sm_m[r];
            float mn = fmaxf(mo, mx);
            float rs = __expf(mo - mn);
            float ssum = 0.f;
            #pragma unroll
            for (int j = 0; j < 32; j += 4) {
                float p0 = __expf(vals[j]   - mn), p1 = __expf(vals[j+1] - mn);
                float p2 = __expf(vals[j+2] - mn), p3 = __expf(vals[j+3] - mn);
                ssum += (p0 + p1) + (p2 + p3);
                *(uint4*)(rowp + j) = make_uint4(f2tf(p0), f2tf(p1), f2tf(p2), f2tf(p3));
            }
            ssum += __shfl_xor_sync(0xffffffffu, ssum, 1);
            if (!half) { sm_l[r] = sm_l[r] * rs + ssum; sm_m[r] = mn; sm_rs[r] = rs; }
        }

        const float* vb = qkv + base + 1024 + (size_t)kt * 64 * QKVW;
        #pragma unroll
        for (int i = 0; i < 8; i++) {
            int kk = t & 63;
            int d4 = (i * 2 + (t >> 6)) * 4;
            float4 v = *(const float4*)(vb + (size_t)kk * QKVW + d4);
            Ks[(d4 + 0) * AP + kk] = f2tf(v.x);
            Ks[(d4 + 1) * AP + kk] = f2tf(v.y);
            Ks[(d4 + 2) * AP + kk] = f2tf(v.z);
            Ks[(d4 + 3) * AP + kk] = f2tf(v.w);
        }
        __syncthreads();

        {
            float rs0 = sm_rs[mrow], rs1 = sm_rs[mrow + 8];
            #pragma unroll
            for (int nt = 0; nt < 8; nt++) {
                co[nt][0] *= rs0; co[nt][1] *= rs0;
                co[nt][2] *= rs1; co[nt][3] *= rs1;
            }
            const uint32_t* Pb = (const uint32_t*)Ps + mrow * AP + lc;
            const uint32_t* Bbase = Ks + gr * AP + lc;
            #pragma unroll
            for (int ks = 0; ks < 8; ks++) {
                uint32_t a[4];
                const uint32_t* p = Pb + ks * 8;
                a[0] = p[0]; a[1] = p[8 * AP]; a[2] = p[4]; a[3] = p[8 * AP + 4];
                #pragma unroll
                for (int nt = 0; nt < 8; nt++) {
                    const uint32_t* q2 = Bbase + nt * 8 * AP + ks * 8;
                    uint32_t b[2] = {q2[0], q2[4]};
                    mma8(co[nt], a, b);
                }
            }
        }
    }

    float inv0 = 1.f / sm_l[mrow], inv1 = 1.f / sm_l[mrow + 8];
    size_t tok = (size_t)bb * SQ + qt * 64;
    #pragma unroll
    for (int nt = 0; nt < 8; nt++) {
        int c = nt * 8 + lc * 2;
        uint32_t hi, lo;
        split2(co[nt][0] * inv0, co[nt][1] * inv0, hi, lo);
        size_t o0 = (tok + mrow) * 256 + hh * 32 + (c >> 1);
        oh[o0] = hi; ol[o0] = lo;
        split2(co[nt][2] * inv1, co[nt][3] * inv1, hi, lo);
        size_t o1 = (tok + mrow + 8) * 256 + hh * 32 + (c >> 1);
        oh[o1] = hi; ol[o1] = lo;
    }
}

// ---------------- weight transpose + split: in[R][C] -> planes [C][R/2] ----------------
__global__ __launch_bounds__(256) void wsplit(const float* __restrict__ in,
                                              uint32_t* __restrict__ oh,
                                              uint32_t* __restrict__ ol,
                                              int R, int C, size_t in_z, size_t o_z) {
    __shared__ float tb[32][33];
    in += blockIdx.z * in_z;
    oh += blockIdx.z * o_z;
    ol += blockIdx.z * o_z;
    int c0 = blockIdx.x * 32, r0 = blockIdx.y * 32;
    int tx = threadIdx.x, ty = threadIdx.y;
    #pragma unroll
    for (int i = 0; i < 32; i += 8)
        tb[ty + i][tx] = in[(size_t)(r0 + ty + i) * C + c0 + tx];
    __syncthreads();
    int R2 = R >> 1;
    for (int j = ty; j < 16; j += 8) {
        uint32_t hi, lo;
        split2(tb[2 * j][tx], tb[2 * j + 1][tx], hi, lo);
        size_t o = (size_t)(c0 + tx) * R2 + (r0 >> 1) + j;
        oh[o] = hi; ol[o] = lo;
    }
}

__global__ __launch_bounds__(256) void biaspack_kernel(const float* __restrict__ bq,
                                                       const float* __restrict__ bk,
                                                       const float* __restrict__ bv,
                                                       float* __restrict__ dst) {
    int idx = blockIdx.x * 256 + threadIdx.x;
    if (idx >= NL * QKVW) return;
    int l = idx / QKVW, j = idx % QKVW;
    float v;
    if (j < 512)       v = bq[l * 512 + j];
    else if (j < 1024) v = bk[l * 512 + j - 512];
    else               v = bv[l * 512 + j - 1024];
    dst[idx] = v;
}

__global__ __launch_bounds__(256) void embed_kernel(const int* __restrict__ ids,
                                                    const float* __restrict__ emb,
                                                    float* __restrict__ x) {
    int idx = blockIdx.x * 256 + threadIdx.x;
    if (idx >= NTOK * DM) return;
    int row = idx >> 9, d = idx & 511, s = row & (SQ - 1);
    int tok = ids[row];
    int i2 = d & ~1;
    float div = expf(-(float)i2 * (9.210340371976184f / 512.0f));
    float ang = (float)s * div;
    float pe = (d & 1) ? cosf(ang) : sinf(ang);
    x[idx] = emb[(size_t)tok * DM + d] + pe;
}

// ---------------- layernorm -> split planes ----------------
__global__ __launch_bounds__(256) void ln_split(const float* __restrict__ x,
                                                const float* __restrict__ w,
                                                const float* __restrict__ bias,
                                                uint32_t* __restrict__ yh,
                                                uint32_t* __restrict__ yl) {
    __shared__ float sred[16];
    int row = blockIdx.x, t = threadIdx.x;
    const float* xr = x + (size_t)row * DM;
    float2 v = *(const float2*)(xr + 2 * t);
    float s = v.x + v.y;
    #pragma unroll
    for (int off = 16; off; off >>= 1) s += __shfl_xor_sync(0xffffffffu, s, off);
    if ((t & 31) == 0) sred[t >> 5] = s;
    __syncthreads();
    float tot = 0.f;
    #pragma unroll
    for (int i = 0; i < 8; i++) tot += sred[i];
    float mu = tot * (1.0f / DM);
    float d0 = v.x - mu, d1 = v.y - mu;
    float s2 = d0 * d0 + d1 * d1;
    #pragma unroll
    for (int off = 16; off; off >>= 1) s2 += __shfl_xor_sync(0xffffffffu, s2, off);
    if ((t & 31) == 0) sred[8 + (t >> 5)] = s2;
    __syncthreads();
    float tot2 = 0.f;
    #pragma unroll
    for (int i = 0; i < 8; i++) tot2 += sred[8 + i];
    float rstd = rsqrtf(tot2 * (1.0f / DM) + 1e-5f);
    float y0 = d0 * rstd * w[2 * t]     + bias[2 * t];
    float y1 = d1 * rstd * w[2 * t + 1] + bias[2 * t + 1];
    uint32_t hi, lo;
    split2(y0, y1, hi, lo);
    yh[(size_t)row * 256 + t] = hi;
    yl[(size_t)row * 256 + t] = lo;
}

// ---------------- host ----------------
static void run_gemm(const uint32_t* Ah, const uint32_t* Al,
                     const uint32_t* Bh, const uint32_t* Bl,
                     const float* bias, const float* R, float* C,
                     uint32_t* Ch, uint32_t* Cl, int K2, int M, int relu) {
    gemm_bs<<<dim3(M / 128, NTOK / 128), 256, GEMM_SMEM>>>(
        Ah, Al, Bh, Bl, bias, R, C, Ch, Cl, K2, M, relu);
}

extern "C" void kernel_launch(void* const* d_in, const int* in_sizes, int n_in,
                              void* d_out, int out_size) {
    (void)in_sizes; (void)n_in; (void)out_size;
    const int*   ids  = (const int*)  d_in[0];
    const float* emb  = (const float*)d_in[1];
    const float* wq   = (const float*)d_in[2];
    const float* bq   = (const float*)d_in[3];
    const float* wk   = (const float*)d_in[4];
    const float* bk   = (const float*)d_in[5];
    const float* wv   = (const float*)d_in[6];
    const float* bv   = (const float*)d_in[7];
    const float* wo   = (const float*)d_in[8];
    const float* bo   = (const float*)d_in[9];
    const float* ln1w = (const float*)d_in[10];
    const float* ln1b = (const float*)d_in[11];
    const float* ln2w = (const float*)d_in[12];
    const float* ln2b = (const float*)d_in[13];
    const float* w1   = (const float*)d_in[14];
    const float* b1   = (const float*)d_in[15];
    const float* w2   = (const float*)d_in[16];
    const float* b2   = (const float*)d_in[17];
    const float* outw = (const float*)d_in[18];
    const float* outb = (const float*)d_in[19];

    float *x, *qkv, *bqkv;
    uint32_t *hh, *hl, *ah, *al, *fh, *fl, *xh, *xl;
    uint32_t *wqkvh, *wqkvl, *woh, *wol, *w1h, *w1l, *w2h, *w2l, *owh, *owl;
    cudaGetSymbolAddress((void**)&x,    g_x);
    cudaGetSymbolAddress((void**)&qkv,  g_qkv);
    cudaGetSymbolAddress((void**)&bqkv, g_bqkv);
    cudaGetSymbolAddress((void**)&hh, g_hh); cudaGetSymbolAddress((void**)&hl, g_hl);
    cudaGetSymbolAddress((void**)&ah, g_ah); cudaGetSymbolAddress((void**)&al, g_al);
    cudaGetSymbolAddress((void**)&fh, g_fh); cudaGetSymbolAddress((void**)&fl, g_fl);
    cudaGetSymbolAddress((void**)&xh, g_xh); cudaGetSymbolAddress((void**)&xl, g_xl);
    cudaGetSymbolAddress((void**)&wqkvh, g_wqkvh); cudaGetSymbolAddress((void**)&wqkvl, g_wqkvl);
    cudaGetSymbolAddress((void**)&woh, g_woh); cudaGetSymbolAddress((void**)&wol, g_wol);
    cudaGetSymbolAddress((void**)&w1h, g_w1h); cudaGetSymbolAddress((void**)&w1l, g_w1l);
    cudaGetSymbolAddress((void**)&w2h, g_w2h); cudaGetSymbolAddress((void**)&w2l, g_w2l);
    cudaGetSymbolAddress((void**)&owh, g_owh); cudaGetSymbolAddress((void**)&owl, g_owl);

    cudaFuncSetAttribute(gemm_bs, cudaFuncAttributeMaxDynamicSharedMemorySize, GEMM_SMEM);
    cudaFuncSetAttribute(attn_mma, cudaFuncAttributeMaxDynamicSharedMemorySize, ATTN_SMEM);

    dim3 tb(32, 8);
    size_t LQ = (size_t)QKVW * 256;   // per-layer plane stride for qkv weights
    wsplit<<<dim3(16, 16, NL), tb>>>(wq, wqkvh,            wqkvl,            DM, DM, (size_t)DM*DM, LQ);
    wsplit<<<dim3(16, 16, NL), tb>>>(wk, wqkvh + 512*256,  wqkvl + 512*256,  DM, DM, (size_t)DM*DM, LQ);
    wsplit<<<dim3(16, 16, NL), tb>>>(wv, wqkvh + 1024*256, wqkvl + 1024*256, DM, DM, (size_t)DM*DM, LQ);
    wsplit<<<dim3(16, 16, NL), tb>>>(wo, woh, wol, DM, DM, (size_t)DM*DM, (size_t)DM*256);
    wsplit<<<dim3(DFF/32, 16, NL), tb>>>(w1, w1h, w1l, DM, DFF, (size_t)DM*DFF, (size_t)DFF*256);
    wsplit<<<dim3(16, DFF/32, NL), tb>>>(w2, w2h, w2l, DFF, DM, (size_t)DM*DFF, (size_t)DM*1024);
    wsplit<<<dim3(NV/32, 16, 1),   tb>>>(outw, owh, owl, DM, NV, 0, 0);
    biaspack_kernel<<<(NL * QKVW + 255) / 256, 256>>>(bq, bk, bv, bqkv);

    embed_kernel<<<(NTOK * DM) / 256, 256>>>(ids, emb, x);

    for (int l = 0; l < NL; l++) {
        size_t offD = (size_t)l * DM;
        size_t offF = (size_t)l * DFF;

        ln_split<<<NTOK, 256>>>(x, ln1w + offD, ln1b + offD, hh, hl);
        run_gemm(hh, hl, wqkvh + l * LQ, wqkvl + l * LQ,
                 bqkv + (size_t)l * QKVW, nullptr, qkv, nullptr, nullptr, 256, QKVW, 0);
        attn_mma<<<dim3(SQ / 64, NB * NH), 128, ATTN_SMEM>>>(qkv, ah, al);
        run_gemm(ah, al, woh + (size_t)l * DM * 256, wol + (size_t)l * DM * 256,
                 bo + offD, nullptr, x, nullptr, nullptr, 256, DM, 0);
        ln_split<<<NTOK, 256>>>(x, ln2w + offD, ln2b + offD, hh, hl);
        run_gemm(hh, hl, w1h + (size_t)l * DFF * 256, w1l + (size_t)l * DFF * 256,
                 b1 + offF, nullptr, nullptr, fh, fl, 256, DFF, 1);
        run_gemm(fh, fl, w2h + (size_t)l * DM * 1024, w2l + (size_t)l * DM * 1024,
                 b2 + offD, x /*residual*/, x, xh, xl, 1024, DM, 0);
    }

    run_gemm(xh, xl, owh, owl, outb, nullptr, (float*)d_out, nullptr, nullptr, 256, NV, 0);
}